// round 8
// baseline (speedup 1.0000x reference)
#include <cuda_runtime.h>
#include <cuda_bf16.h>
#include <math.h>
#include <stdint.h>

#define NQ       2048
#define ND       100000
#define DIM      16
#define QTILES   16            // 2048 / 128 queries per CTA
#define DS       37            // data splits; 16*37 = 592 CTAs = 4/SM
#define TILE     256           // data points per smem tile
#define NT       11            // tiles per split
#define PTS_PER_SPLIT (TILE * NT)            // 2816
#define NPAD     (DS * PTS_PER_SPLIT)        // 104192
#define THREADS  256
#define PREP_BLOCKS  814       // NPAD / 128 exactly (2 threads per point)
#define PREP_THREADS 256
#define PROW     80            // padded partials row (74 used)

// ---- device scratch (no allocations allowed) ----
// g_dcat: per point, 16 tf32 words, PERMUTED: pos 4g+{0..3} = natural words
//         {g, g+4, g+8, g+12}. One LDS.128 per lane yields both k8 B
//         fragments (b0_kc0, b1_kc0, b0_kc1, b1_kc1) for m16n8k8 tf32.
__device__ float4 g_dcat[(size_t)NPAD * 4];
__device__ float g_xcat[(size_t)NQ * 16];   // y = x*log2e, tf32-rounded
__device__ float g_coeff[NPAD];             // w_j * exp(-0.5*||d||^2)
__device__ float g_partials[(size_t)NQ * PROW];
__device__ float g_wpart[PREP_BLOCKS];

// ---- helpers ----
__device__ __forceinline__ uint32_t s2u(const void* p) {
    uint32_t a;
    asm("{ .reg .u64 t; cvta.to.shared.u64 t, %1; cvt.u32.u64 %0, t; }"
        : "=r"(a) : "l"(p));
    return a;
}
__device__ __forceinline__ void cpa16(uint32_t dst, const void* src) {
    asm volatile("cp.async.cg.shared.global [%0], [%1], 16;"
                 :: "r"(dst), "l"(src));
}
#define CP_COMMIT() asm volatile("cp.async.commit_group;" ::: "memory")
#define CP_WAIT0()  asm volatile("cp.async.wait_group 0;" ::: "memory")
#define CP_WAIT1()  asm volatile("cp.async.wait_group 1;" ::: "memory")

__device__ __forceinline__ float ex2f(float x) {
    float r; asm("ex2.approx.f32 %0, %1;" : "=f"(r) : "f"(x)); return r;
}
// exp2 on the fma pipe: magic-number rint + deg-5 poly + integer exponent add.
// Valid for x in [-120, 120]; inputs here are bounded |x| < ~80.
__device__ __forceinline__ float exp2poly(float x) {
    float xm = fmaxf(x, -120.0f);
    float t  = xm + 12582912.0f;            // 1.5*2^23: RN-to-integer
    int   e  = __float_as_int(t);           // integer in low mantissa bits
    float fl = t - 12582912.0f;
    float f  = xm - fl;                     // [-0.5, 0.5]
    float p  = 1.3333558e-3f;
    p = fmaf(p, f, 9.6181291e-3f);
    p = fmaf(p, f, 5.5504109e-2f);
    p = fmaf(p, f, 2.4022651e-1f);
    p = fmaf(p, f, 6.9314718e-1f);
    p = fmaf(p, f, 1.0f);
    return __int_as_float(__float_as_int(p) + (e << 23));
}
__device__ __forceinline__ float tf32r(float x) {
    float r; asm("cvt.rna.tf32.f32 %0, %1;" : "=f"(r) : "f"(x)); return r;
}
__device__ __forceinline__ void mma_tf32(float* d, const uint32_t* a,
                                         uint32_t b0, uint32_t b1) {
    asm volatile(
        "mma.sync.aligned.m16n8k8.row.col.f32.tf32.tf32.f32 "
        "{%0,%1,%2,%3}, {%4,%5,%6,%7}, {%8,%9}, {%0,%1,%2,%3};"
        : "+f"(d[0]), "+f"(d[1]), "+f"(d[2]), "+f"(d[3])
        : "r"(a[0]), "r"(a[1]), "r"(a[2]), "r"(a[3]), "r"(b0), "r"(b1));
}
__device__ __forceinline__ void lds128(uint32_t addr, uint32_t* v) {
    asm volatile("ld.shared.v4.u32 {%0,%1,%2,%3}, [%4];"
                 : "=r"(v[0]), "=r"(v[1]), "=r"(v[2]), "=r"(v[3]) : "r"(addr));
}

// ---------------------------------------------------------------------------
// Prep: TWO threads per point (half = low bit). Each loads 8 dims, tf32-
// rounds, pair-exchanges via shfl for the permuted store; pair-sum for ||d||^2.
// Thread with global slot < NQ also preps query slot (full 16 dims).
// ---------------------------------------------------------------------------
__global__ __launch_bounds__(PREP_THREADS)
void kde_prep_kernel(const float* __restrict__ data,
                     const float* __restrict__ w,
                     const float* __restrict__ X) {
    int t = threadIdx.x;
    int gp = blockIdx.x * PREP_THREADS + t;   // half-slot, < NPAD*2
    int j = gp >> 1, half = gp & 1;

    float4 a = make_float4(0.f, 0.f, 0.f, 0.f);
    float4 b = make_float4(0.f, 0.f, 0.f, 0.f);
    float wj = 0.0f;
    if (j < ND) {
        const float4* src = (const float4*)(data + (size_t)j * DIM + half * 8);
        a = src[0]; b = src[1];
        if (half == 0) wj = w[j];
    }
    float dn = a.x * a.x + a.y * a.y + a.z * a.z + a.w * a.w
             + b.x * b.x + b.y * b.y + b.z * b.z + b.w * b.w;
    dn += __shfl_xor_sync(0xFFFFFFFFu, dn, 1);
    if (half == 0) g_coeff[j] = wj * __expf(-0.5f * dn);

    // local tf32 words: wl[i] = dim half*8 + i
    float wl[8];
    wl[0] = tf32r(a.x); wl[1] = tf32r(a.y); wl[2] = tf32r(a.z); wl[3] = tf32r(a.w);
    wl[4] = tf32r(b.x); wl[5] = tf32r(b.y); wl[6] = tf32r(b.z); wl[7] = tf32r(b.w);

    // exchange: half0 sends wl{2,3,6,7}, receives partner wl{0,1,4,5};
    //           half1 sends wl{0,1,4,5}, receives partner wl{2,3,6,7}.
    float s0 = half ? wl[0] : wl[2];
    float s1 = half ? wl[1] : wl[3];
    float s2 = half ? wl[4] : wl[6];
    float s3 = half ? wl[5] : wl[7];
    float r0 = __shfl_xor_sync(0xFFFFFFFFu, s0, 1);
    float r1 = __shfl_xor_sync(0xFFFFFFFFu, s1, 1);
    float r2 = __shfl_xor_sync(0xFFFFFFFFu, s2, 1);
    float r3 = __shfl_xor_sync(0xFFFFFFFFu, s3, 1);

    // permuted output groups: half0 -> g=0,1 ; half1 -> g=2,3
    float4 o0, o1;
    if (half == 0) {
        // g=0: dims {0,4,8,12}; g=1: dims {1,5,9,13}
        o0 = make_float4(wl[0], wl[4], r0, r2);
        o1 = make_float4(wl[1], wl[5], r1, r3);
    } else {
        // g=2: dims {2,6,10,14}; g=3: dims {3,7,11,15}
        o0 = make_float4(r0, r2, wl[2], wl[6]);
        o1 = make_float4(r1, r3, wl[3], wl[7]);
    }
    g_dcat[(size_t)j * 4 + half * 2 + 0] = o0;
    g_dcat[(size_t)j * 4 + half * 2 + 1] = o1;

    // query prep: slot gp handles query gp (16 dims)
    if (gp < NQ) {
        const float LOG2E = 1.4426950408889634f;
        const float4* src = (const float4*)(X + (size_t)gp * DIM);
        float4* dst = (float4*)(g_xcat + (size_t)gp * 16);
#pragma unroll
        for (int v = 0; v < 4; v++) {
            float4 p = src[v];
            float4 o;
            o.x = tf32r(p.x * LOG2E);
            o.y = tf32r(p.y * LOG2E);
            o.z = tf32r(p.z * LOG2E);
            o.w = tf32r(p.w * LOG2E);
            dst[v] = o;
        }
    }

    __shared__ float red[PREP_THREADS];
    red[t] = wj;
    __syncthreads();
#pragma unroll
    for (int s = PREP_THREADS / 2; s > 0; s >>= 1) {
        if (t < s) red[t] += red[t + s];
        __syncthreads();
    }
    if (t == 0) g_wpart[blockIdx.x] = red[0];
}

// ---------------------------------------------------------------------------
// Main: CTA (qt, ds): 128 queries x 2816 points, tf32 m16n8k8.
//   Warp w: wm = w>>1 (32 queries = 2 m-tiles), wn = w&1 (128 points).
//   Per 8-pt n-tile: 1 LDS.128 -> both k8 B fragments; 2 MMAs per m-tile.
//   Epilogue: 8 exps -> 6.5 on MUFU ex2, 1.5 on fma-pipe polynomial
//   (d1[3] every nt, d1[1] on odd nt) to balance the two pipes.
// ---------------------------------------------------------------------------
__global__ __launch_bounds__(THREADS, 4)
void kde_main_kernel() {
    __shared__ uint4 sd[2][TILE * 4];   // 2 x 16 KB, 64B per point (permuted)
    __shared__ float sc[2][TILE];

    int tid = threadIdx.x;
    int w = tid >> 5, lane = tid & 31;
    int wm = w >> 1, wn = w & 1;
    int qt = blockIdx.x, ds = blockIdx.y;
    int p0base = ds * PTS_PER_SPLIT;
    int r = lane >> 2, cg = lane & 3, c2 = cg * 2;

    // A fragments: 32 queries (2 m-tiles) x 2 k-chunks, tf32
    int qb = qt * 128 + wm * 32;
    uint32_t afrag[2][2][4];
#pragma unroll
    for (int mt = 0; mt < 2; mt++)
#pragma unroll
        for (int kc = 0; kc < 2; kc++) {
            const uint32_t* base =
                (const uint32_t*)g_xcat + (size_t)(qb + mt * 16 + r) * 16 + kc * 8 + cg;
            afrag[mt][kc][0] = base[0];
            afrag[mt][kc][1] = base[8 * 16];
            afrag[mt][kc][2] = base[4];
            afrag[mt][kc][3] = base[8 * 16 + 4];
        }

    // Stage tile 0
    {
        const char* bsrc = (const char*)(g_dcat + (size_t)p0base * 4);
        uint32_t sbb = s2u(sd[0]);
#pragma unroll
        for (int i = tid; i < TILE * 4; i += THREADS)
            cpa16(sbb + i * 16, bsrc + i * 16);
        if (tid < 64)
            cpa16(s2u(sc[0]) + tid * 16, (const char*)(g_coeff + p0base) + tid * 16);
        CP_COMMIT();
    }

    float acc[2][2] = {{0.0f, 0.0f}, {0.0f, 0.0f}};
    int buf = 0;

    for (int it = 0; it < NT; ++it) {
        if (it + 1 < NT) {
            int p0 = p0base + (it + 1) * TILE;
            const char* bsrc = (const char*)(g_dcat + (size_t)p0 * 4);
            uint32_t sbb = s2u(sd[buf ^ 1]);
#pragma unroll
            for (int i = tid; i < TILE * 4; i += THREADS)
                cpa16(sbb + i * 16, bsrc + i * 16);
            if (tid < 64)
                cpa16(s2u(sc[buf ^ 1]) + tid * 16, (const char*)(g_coeff + p0) + tid * 16);
            CP_COMMIT();
            CP_WAIT1();   // tile `it` resident
        } else {
            CP_WAIT0();
        }
        __syncthreads();

        uint32_t sdb = s2u(sd[buf]);
        const float* scf = sc[buf];
#pragma unroll
        for (int nt = 0; nt < 16; nt++) {
            int n0 = wn * 128 + nt * 8;
            uint32_t b[4];
            lds128(sdb + (uint32_t)(n0 + r) * 64 + (uint32_t)cg * 16, b);
            float d0[4] = {0, 0, 0, 0}, d1[4] = {0, 0, 0, 0};
            // b[0],b[1] = k-chunk 0 fragment; b[2],b[3] = k-chunk 1
            mma_tf32(d0, afrag[0][0], b[0], b[1]);
            mma_tf32(d1, afrag[1][0], b[0], b[1]);
            mma_tf32(d0, afrag[0][1], b[2], b[3]);
            mma_tf32(d1, afrag[1][1], b[2], b[3]);

            float2 cj = *(const float2*)(scf + n0 + c2);
            acc[0][0] = fmaf(cj.x, ex2f(d0[0]), acc[0][0]);
            acc[0][0] = fmaf(cj.y, ex2f(d0[1]), acc[0][0]);
            acc[0][1] = fmaf(cj.x, ex2f(d0[2]), acc[0][1]);
            acc[0][1] = fmaf(cj.y, ex2f(d0[3]), acc[0][1]);
            acc[1][0] = fmaf(cj.x, ex2f(d1[0]), acc[1][0]);
            float e11 = (nt & 1) ? exp2poly(d1[1]) : ex2f(d1[1]);
            acc[1][0] = fmaf(cj.y, e11, acc[1][0]);
            acc[1][1] = fmaf(cj.x, ex2f(d1[2]), acc[1][1]);
            acc[1][1] = fmaf(cj.y, exp2poly(d1[3]), acc[1][1]);
        }
        __syncthreads();  // done reading buf before restage
        buf ^= 1;
    }

    // Reduce over the 4 column-lanes (fixed order, deterministic)
#pragma unroll
    for (int mt = 0; mt < 2; mt++)
#pragma unroll
        for (int hh = 0; hh < 2; hh++) {
            float v = acc[mt][hh];
            v += __shfl_xor_sync(0xFFFFFFFFu, v, 1);
            v += __shfl_xor_sync(0xFFFFFFFFu, v, 2);
            acc[mt][hh] = v;
        }
    if (cg == 0) {
        int col = ds * 2 + wn;
        g_partials[(size_t)(qb + r) * PROW + col]          = acc[0][0];
        g_partials[(size_t)(qb + r + 8) * PROW + col]      = acc[0][1];
        g_partials[(size_t)(qb + 16 + r) * PROW + col]     = acc[1][0];
        g_partials[(size_t)(qb + 16 + r + 8) * PROW + col] = acc[1][1];
    }
}

// ---------------------------------------------------------------------------
// Finalize: warp per query. Each block also reduces g_wpart -> logsumw.
//   log_density = log(S) - 0.5||x||^2 - 8*log(2*pi) - logsumw
// ---------------------------------------------------------------------------
__global__ __launch_bounds__(256)
void kde_final_kernel(const float* __restrict__ X,
                      float* __restrict__ out) {
    __shared__ float red[256];
    __shared__ float s_logsumw;
    int t = threadIdx.x;
    int w = t >> 5, lane = t & 31;

    float s = g_wpart[t] + g_wpart[t + 256];
    if (t + 512 < PREP_BLOCKS) s += g_wpart[t + 512];
    red[t] = s;
    __syncthreads();
#pragma unroll
    for (int st = 128; st > 0; st >>= 1) {
        if (t < st) red[t] += red[t + st];
        __syncthreads();
    }
    if (t == 0) s_logsumw = logf(red[0]);
    __syncthreads();

    int q = blockIdx.x * 8 + w;
    const float* pr = g_partials + (size_t)q * PROW;
    float S = pr[lane] + pr[lane + 32];
    if (lane < DS * 2 - 64) S += pr[lane + 64];
    // fixed-order shfl reduction
    S += __shfl_xor_sync(0xFFFFFFFFu, S, 16);
    S += __shfl_xor_sync(0xFFFFFFFFu, S, 8);
    S += __shfl_xor_sync(0xFFFFFFFFu, S, 4);
    S += __shfl_xor_sync(0xFFFFFFFFu, S, 2);
    S += __shfl_xor_sync(0xFFFFFFFFu, S, 1);

    if (lane == 0) {
        float qn = 0.0f;
        const float4* row = (const float4*)(X + (size_t)q * DIM);
#pragma unroll
        for (int v = 0; v < 4; v++) {
            float4 p = row[v];
            qn += p.x * p.x + p.y * p.y + p.z * p.z + p.w * p.w;
        }
        const float LOG2PI = 1.8378770664093453f;
        out[q] = logf(S) - 0.5f * qn - 8.0f * LOG2PI - s_logsumw;
    }
}

// ---------------------------------------------------------------------------
extern "C" void kernel_launch(void* const* d_in, const int* in_sizes, int n_in,
                              void* d_out, int out_size) {
    const float* X    = (const float*)d_in[0];  // [2048, 16]
    const float* data = (const float*)d_in[1];  // [100000, 16]
    const float* w    = (const float*)d_in[2];  // [100000]
    float* out = (float*)d_out;                 // [2048]

    kde_prep_kernel<<<PREP_BLOCKS, PREP_THREADS>>>(data, w, X);
    kde_main_kernel<<<dim3(QTILES, DS), THREADS>>>();
    kde_final_kernel<<<NQ / 8, 256>>>(X, out);
}

// round 9
// speedup vs baseline: 1.0304x; 1.0304x over previous
#include <cuda_runtime.h>
#include <cuda_bf16.h>
#include <math.h>
#include <stdint.h>

#define NQ       2048
#define ND       100000
#define DIM      16
#define QTILES   16            // 2048 / 128 queries per CTA
#define DS       37            // data splits; 16*37 = 592 CTAs = 4/SM
#define TILE     256           // data points per smem tile
#define NT       11            // tiles per split
#define PTS_PER_SPLIT (TILE * NT)            // 2816
#define THREADS  256
#define PROW     80            // padded partials row (74 used)

// ---- device scratch (no allocations allowed) ----
__device__ float g_partials[(size_t)NQ * PROW];
__device__ float g_wpart[DS];

// ---- helpers ----
__device__ __forceinline__ float ex2f(float x) {
    float r; asm("ex2.approx.f32 %0, %1;" : "=f"(r) : "f"(x)); return r;
}
__device__ __forceinline__ float tf32r(float x) {
    float r; asm("cvt.rna.tf32.f32 %0, %1;" : "=f"(r) : "f"(x)); return r;
}
__device__ __forceinline__ void mma_tf32(float* d, const uint32_t* a,
                                         uint32_t b0, uint32_t b1) {
    asm volatile(
        "mma.sync.aligned.m16n8k8.row.col.f32.tf32.tf32.f32 "
        "{%0,%1,%2,%3}, {%4,%5,%6,%7}, {%8,%9}, {%0,%1,%2,%3};"
        : "+f"(d[0]), "+f"(d[1]), "+f"(d[2]), "+f"(d[3])
        : "r"(a[0]), "r"(a[1]), "r"(a[2]), "r"(a[3]), "r"(b0), "r"(b1));
}
__device__ __forceinline__ void lds128(uint32_t addr, uint32_t* v) {
    asm volatile("ld.shared.v4.u32 {%0,%1,%2,%3}, [%4];"
                 : "=r"(v[0]), "=r"(v[1]), "=r"(v[2]), "=r"(v[3]) : "r"(addr));
}
__device__ __forceinline__ uint32_t s2u(const void* p) {
    uint32_t a;
    asm("{ .reg .u64 t; cvta.to.shared.u64 t, %1; cvt.u32.u64 %0, t; }"
        : "=r"(a) : "l"(p));
    return a;
}

// ---------------------------------------------------------------------------
// Main (fused): CTA (qt, ds): 128 queries x 2816 points, tf32 m16n8k8.
//   Staging is fused: each thread LDGs one RAW fp32 point per tile,
//   tf32-rounds, permutes in registers, STSs the 64B fragment-ready layout,
//   and computes coeff = w * exp(-||d||^2/2) in place.
//   Warp w: wm = w>>1 (32 queries = 2 m-tiles), wn = w&1 (128 points).
//   Per 8-pt n-tile: 1 LDS.128 -> both k8 B fragments; 2 MMAs per m-tile;
//   epilogue 8x (MUFU ex2 + FFMA accumulate).
// ---------------------------------------------------------------------------
__global__ __launch_bounds__(THREADS, 4)
void kde_main_kernel(const float* __restrict__ X,
                     const float* __restrict__ data,
                     const float* __restrict__ wvec) {
    __shared__ uint4 sd[2][TILE * 4];   // 2 x 16 KB, 64B per point (permuted)
    __shared__ float sc[2][TILE];       // coeffs

    int tid = threadIdx.x;
    int w = tid >> 5, lane = tid & 31;
    int wm = w >> 1, wn = w & 1;
    int qt = blockIdx.x, ds = blockIdx.y;
    int p0base = ds * PTS_PER_SPLIT;
    int r = lane >> 2, cg = lane & 3, c2 = cg * 2;

    const float LOG2E = 1.4426950408889634f;

    // A fragments directly from X: y = x * log2e, tf32-rounded.
    int qb = qt * 128 + wm * 32;
    uint32_t afrag[2][2][4];
#pragma unroll
    for (int mt = 0; mt < 2; mt++)
#pragma unroll
        for (int kc = 0; kc < 2; kc++) {
            int q0 = qb + mt * 16 + r;
            int k0 = kc * 8 + cg;
            afrag[mt][kc][0] = __float_as_uint(tf32r(X[(size_t)q0 * 16 + k0] * LOG2E));
            afrag[mt][kc][1] = __float_as_uint(tf32r(X[(size_t)(q0 + 8) * 16 + k0] * LOG2E));
            afrag[mt][kc][2] = __float_as_uint(tf32r(X[(size_t)q0 * 16 + k0 + 4] * LOG2E));
            afrag[mt][kc][3] = __float_as_uint(tf32r(X[(size_t)(q0 + 8) * 16 + k0 + 4] * LOG2E));
        }

    // Staging registers (one point = 64 bytes)
    float4 ra, rb2, rc, rd;
    float rw;
    float wsum = 0.0f;

    // ---- stage helpers (macros keep everything in registers) ----
#define LOAD_PT(IT)                                                         \
    {                                                                       \
        int j = p0base + (IT) * TILE + tid;                                 \
        if (j < ND) {                                                       \
            const float4* src = (const float4*)(data + (size_t)j * DIM);    \
            ra = src[0]; rb2 = src[1]; rc = src[2]; rd = src[3];            \
            rw = wvec[j];                                                   \
        } else {                                                            \
            ra = rb2 = rc = rd = make_float4(0.f, 0.f, 0.f, 0.f);           \
            rw = 0.0f;                                                      \
        }                                                                   \
    }

#define STORE_PT(BUF)                                                       \
    {                                                                       \
        float e[16];                                                        \
        e[0]=ra.x; e[1]=ra.y; e[2]=ra.z; e[3]=ra.w;                         \
        e[4]=rb2.x; e[5]=rb2.y; e[6]=rb2.z; e[7]=rb2.w;                     \
        e[8]=rc.x; e[9]=rc.y; e[10]=rc.z; e[11]=rc.w;                       \
        e[12]=rd.x; e[13]=rd.y; e[14]=rd.z; e[15]=rd.w;                     \
        float dn = 0.0f;                                                    \
        _Pragma("unroll")                                                   \
        for (int k = 0; k < 16; k++) dn = fmaf(e[k], e[k], dn);             \
        sc[BUF][tid] = rw * ex2f(-0.72134752f * dn);                        \
        _Pragma("unroll")                                                   \
        for (int g = 0; g < 4; g++) {                                       \
            float4 o;                                                       \
            o.x = tf32r(e[g]); o.y = tf32r(e[g + 4]);                       \
            o.z = tf32r(e[g + 8]); o.w = tf32r(e[g + 12]);                  \
            sd[BUF][tid * 4 + g] = *(uint4*)&o;                             \
        }                                                                   \
        wsum += rw;                                                         \
    }

    // Prologue: stage tile 0, issue load for tile 1
    LOAD_PT(0);
    STORE_PT(0);
    LOAD_PT(1);
    __syncthreads();

    float acc[2][2] = {{0.0f, 0.0f}, {0.0f, 0.0f}};
    int buf = 0;

    for (int it = 0; it < NT; ++it) {
        // ---- compute on sd[buf] / sc[buf] ----
        uint32_t sdb = s2u(sd[buf]);
        const float* scf = sc[buf];
#pragma unroll
        for (int nt = 0; nt < 16; nt++) {
            int n0 = wn * 128 + nt * 8;
            uint32_t b[4];
            lds128(sdb + (uint32_t)(n0 + r) * 64 + (uint32_t)cg * 16, b);
            float d0[4] = {0, 0, 0, 0}, d1[4] = {0, 0, 0, 0};
            mma_tf32(d0, afrag[0][0], b[0], b[1]);
            mma_tf32(d1, afrag[1][0], b[0], b[1]);
            mma_tf32(d0, afrag[0][1], b[2], b[3]);
            mma_tf32(d1, afrag[1][1], b[2], b[3]);

            float2 cj = *(const float2*)(scf + n0 + c2);
            acc[0][0] = fmaf(cj.x, ex2f(d0[0]), acc[0][0]);
            acc[0][0] = fmaf(cj.y, ex2f(d0[1]), acc[0][0]);
            acc[0][1] = fmaf(cj.x, ex2f(d0[2]), acc[0][1]);
            acc[0][1] = fmaf(cj.y, ex2f(d0[3]), acc[0][1]);
            acc[1][0] = fmaf(cj.x, ex2f(d1[0]), acc[1][0]);
            acc[1][0] = fmaf(cj.y, ex2f(d1[1]), acc[1][0]);
            acc[1][1] = fmaf(cj.x, ex2f(d1[2]), acc[1][1]);
            acc[1][1] = fmaf(cj.y, ex2f(d1[3]), acc[1][1]);
        }

        // ---- stage tile it+1 into the other buffer, prefetch it+2 ----
        if (it + 1 < NT) STORE_PT(buf ^ 1);
        if (it + 2 < NT) LOAD_PT(it + 2);
        __syncthreads();   // staging of buf^1 done; everyone done reading buf
        buf ^= 1;
    }

    // Σw for this split (only qt==0 CTA publishes; all compute identically)
    if (qt == 0) {
        __shared__ float red[THREADS];
        red[tid] = wsum;
        __syncthreads();
#pragma unroll
        for (int s = THREADS / 2; s > 0; s >>= 1) {
            if (tid < s) red[tid] += red[tid + s];
            __syncthreads();
        }
        if (tid == 0) g_wpart[ds] = red[0];
    }

    // Reduce over the 4 column-lanes (fixed order, deterministic)
#pragma unroll
    for (int mt = 0; mt < 2; mt++)
#pragma unroll
        for (int hh = 0; hh < 2; hh++) {
            float v = acc[mt][hh];
            v += __shfl_xor_sync(0xFFFFFFFFu, v, 1);
            v += __shfl_xor_sync(0xFFFFFFFFu, v, 2);
            acc[mt][hh] = v;
        }
    if (cg == 0) {
        int col = ds * 2 + wn;
        g_partials[(size_t)(qb + r) * PROW + col]          = acc[0][0];
        g_partials[(size_t)(qb + r + 8) * PROW + col]      = acc[0][1];
        g_partials[(size_t)(qb + 16 + r) * PROW + col]     = acc[1][0];
        g_partials[(size_t)(qb + 16 + r + 8) * PROW + col] = acc[1][1];
    }
#undef LOAD_PT
#undef STORE_PT
}

// ---------------------------------------------------------------------------
// Finalize: warp per query; logsumw from the 37 per-split sums.
//   log_density = log(S) - 0.5||x||^2 - 8*log(2*pi) - logsumw
// ---------------------------------------------------------------------------
__global__ __launch_bounds__(256)
void kde_final_kernel(const float* __restrict__ X,
                      float* __restrict__ out) {
    __shared__ float s_logsumw;
    int t = threadIdx.x;
    int w = t >> 5, lane = t & 31;

    if (w == 0) {
        float s = (lane < DS) ? g_wpart[lane] : 0.0f;
        if (lane + 32 < DS) s += g_wpart[lane + 32];
        s += __shfl_xor_sync(0xFFFFFFFFu, s, 16);
        s += __shfl_xor_sync(0xFFFFFFFFu, s, 8);
        s += __shfl_xor_sync(0xFFFFFFFFu, s, 4);
        s += __shfl_xor_sync(0xFFFFFFFFu, s, 2);
        s += __shfl_xor_sync(0xFFFFFFFFu, s, 1);
        if (lane == 0) s_logsumw = logf(s);
    }
    __syncthreads();

    int q = blockIdx.x * 8 + w;
    const float* pr = g_partials + (size_t)q * PROW;
    float S = pr[lane] + pr[lane + 32];
    if (lane < DS * 2 - 64) S += pr[lane + 64];
    // fixed-order shfl reduction
    S += __shfl_xor_sync(0xFFFFFFFFu, S, 16);
    S += __shfl_xor_sync(0xFFFFFFFFu, S, 8);
    S += __shfl_xor_sync(0xFFFFFFFFu, S, 4);
    S += __shfl_xor_sync(0xFFFFFFFFu, S, 2);
    S += __shfl_xor_sync(0xFFFFFFFFu, S, 1);

    if (lane == 0) {
        float qn = 0.0f;
        const float4* row = (const float4*)(X + (size_t)q * DIM);
#pragma unroll
        for (int v = 0; v < 4; v++) {
            float4 p = row[v];
            qn += p.x * p.x + p.y * p.y + p.z * p.z + p.w * p.w;
        }
        const float LOG2PI = 1.8378770664093453f;
        out[q] = logf(S) - 0.5f * qn - 8.0f * LOG2PI - s_logsumw;
    }
}

// ---------------------------------------------------------------------------
extern "C" void kernel_launch(void* const* d_in, const int* in_sizes, int n_in,
                              void* d_out, int out_size) {
    const float* X    = (const float*)d_in[0];  // [2048, 16]
    const float* data = (const float*)d_in[1];  // [100000, 16]
    const float* w    = (const float*)d_in[2];  // [100000]
    float* out = (float*)d_out;                 // [2048]

    kde_main_kernel<<<dim3(QTILES, DS), THREADS>>>(X, data, w);
    kde_final_kernel<<<NQ / 8, 256>>>(X, out);
}

// round 10
// speedup vs baseline: 1.1317x; 1.0983x over previous
#include <cuda_runtime.h>
#include <cuda_bf16.h>
#include <math.h>
#include <stdint.h>

#define NQ       2048
#define ND       100000
#define DIM      16
#define QTILES   16            // 2048 / 128 queries per CTA
#define DS       37            // data splits; 16*37 = 592 CTAs = 4/SM
#define TILE     256           // data points per smem tile
#define NT       11            // tiles per split
#define PTS_PER_SPLIT (TILE * NT)            // 2816
#define NPAD     (DS * PTS_PER_SPLIT)        // 104192
#define THREADS  256
#define PREP_BLOCKS  407       // NPAD / 256 exactly
#define PREP_THREADS 256
#define NCOL     (DS * 2)      // 74 partial columns

// ---- device scratch (no allocations allowed) ----
// g_dcat: per point, 16 tf32 words, PERMUTED: pos 4g+{0..3} = natural words
//         {g, g+4, g+8, g+12}. One LDS.128 per lane yields both k8 B
//         fragments for m16n8k8 tf32.
__device__ float4 g_dcat[(size_t)NPAD * 4];
__device__ float g_xcat[(size_t)NQ * 16];   // y = x*log2e, tf32-rounded
__device__ float g_coeff[NPAD];             // w_j * exp(-0.5*||d||^2)
__device__ float g_partials[(size_t)NCOL * NQ];   // col-major [col][q]
__device__ float g_wpart[PREP_BLOCKS];
__device__ unsigned g_cnt[QTILES];          // arrival counters (wrap -> 0)

// ---- helpers ----
__device__ __forceinline__ uint32_t s2u(const void* p) {
    uint32_t a;
    asm("{ .reg .u64 t; cvta.to.shared.u64 t, %1; cvt.u32.u64 %0, t; }"
        : "=r"(a) : "l"(p));
    return a;
}
__device__ __forceinline__ void cpa16(uint32_t dst, const void* src) {
    asm volatile("cp.async.cg.shared.global [%0], [%1], 16;"
                 :: "r"(dst), "l"(src));
}
#define CP_COMMIT() asm volatile("cp.async.commit_group;" ::: "memory")
#define CP_WAIT0()  asm volatile("cp.async.wait_group 0;" ::: "memory")
#define CP_WAIT1()  asm volatile("cp.async.wait_group 1;" ::: "memory")

__device__ __forceinline__ float ex2f(float x) {
    float r; asm("ex2.approx.f32 %0, %1;" : "=f"(r) : "f"(x)); return r;
}
__device__ __forceinline__ float tf32r(float x) {
    float r; asm("cvt.rna.tf32.f32 %0, %1;" : "=f"(r) : "f"(x)); return r;
}
__device__ __forceinline__ void mma_tf32(float* d, const uint32_t* a,
                                         uint32_t b0, uint32_t b1) {
    asm volatile(
        "mma.sync.aligned.m16n8k8.row.col.f32.tf32.tf32.f32 "
        "{%0,%1,%2,%3}, {%4,%5,%6,%7}, {%8,%9}, {%0,%1,%2,%3};"
        : "+f"(d[0]), "+f"(d[1]), "+f"(d[2]), "+f"(d[3])
        : "r"(a[0]), "r"(a[1]), "r"(a[2]), "r"(a[3]), "r"(b0), "r"(b1));
}
__device__ __forceinline__ void lds128(uint32_t addr, uint32_t* v) {
    asm volatile("ld.shared.v4.u32 {%0,%1,%2,%3}, [%4];"
                 : "=r"(v[0]), "=r"(v[1]), "=r"(v[2]), "=r"(v[3]) : "r"(addr));
}

// ---------------------------------------------------------------------------
// Prep: point j -> tf32 permuted layout + coeff; query j (j<NQ) ->
// y = x*log2e tf32; block-partial sums of w.  (R7-proven structure.)
// ---------------------------------------------------------------------------
__global__ __launch_bounds__(PREP_THREADS)
void kde_prep_kernel(const float* __restrict__ data,
                     const float* __restrict__ w,
                     const float* __restrict__ X) {
    int t = threadIdx.x;
    int j = blockIdx.x * PREP_THREADS + t;   // < NPAD (grid exact)

    float wd[16];
    float cj = 0.0f, wj = 0.0f;
    if (j < ND) {
        const float4* src = (const float4*)(data + (size_t)j * DIM);
        float dn = 0.0f;
#pragma unroll
        for (int v = 0; v < 4; v++) {
            float4 p = src[v];
            dn += p.x * p.x + p.y * p.y + p.z * p.z + p.w * p.w;
            wd[v * 4 + 0] = tf32r(p.x);
            wd[v * 4 + 1] = tf32r(p.y);
            wd[v * 4 + 2] = tf32r(p.z);
            wd[v * 4 + 3] = tf32r(p.w);
        }
        wj = w[j];
        cj = wj * __expf(-0.5f * dn);
    } else {
#pragma unroll
        for (int k = 0; k < 16; k++) wd[k] = 0.0f;
    }
    g_coeff[j] = cj;
    // permuted store: pos 4g+{0..3} = wd[g], wd[g+4], wd[g+8], wd[g+12]
#pragma unroll
    for (int g = 0; g < 4; g++) {
        float4 o;
        o.x = wd[g]; o.y = wd[g + 4]; o.z = wd[g + 8]; o.w = wd[g + 12];
        g_dcat[(size_t)j * 4 + g] = o;
    }

    if (j < NQ) {
        const float LOG2E = 1.4426950408889634f;
        const float4* src = (const float4*)(X + (size_t)j * DIM);
        float4* dst = (float4*)(g_xcat + (size_t)j * 16);
#pragma unroll
        for (int v = 0; v < 4; v++) {
            float4 p = src[v];
            float4 o;
            o.x = tf32r(p.x * LOG2E);
            o.y = tf32r(p.y * LOG2E);
            o.z = tf32r(p.z * LOG2E);
            o.w = tf32r(p.w * LOG2E);
            dst[v] = o;
        }
    }

    __shared__ float red[PREP_THREADS];
    red[t] = wj;
    __syncthreads();
#pragma unroll
    for (int s = PREP_THREADS / 2; s > 0; s >>= 1) {
        if (t < s) red[t] += red[t + s];
        __syncthreads();
    }
    if (t == 0) g_wpart[blockIdx.x] = red[0];
}

// ---------------------------------------------------------------------------
// Main: CTA (qt, ds): 128 queries x 2816 points, tf32 m16n8k8 (R7 loop).
// After storing partials, last-arriving CTA per qt finalizes its 128 queries
// (fixed-order sums -> deterministic output regardless of arrival order).
// ---------------------------------------------------------------------------
__global__ __launch_bounds__(THREADS, 4)
void kde_main_kernel(const float* __restrict__ X, float* __restrict__ out) {
    __shared__ uint4 sd[2][TILE * 4];   // 2 x 16 KB, 64B per point (permuted)
    __shared__ float sc[2][TILE];

    int tid = threadIdx.x;
    int w = tid >> 5, lane = tid & 31;
    int wm = w >> 1, wn = w & 1;
    int qt = blockIdx.x, ds = blockIdx.y;
    int p0base = ds * PTS_PER_SPLIT;
    int r = lane >> 2, cg = lane & 3, c2 = cg * 2;

    // A fragments: 32 queries (2 m-tiles) x 2 k-chunks, tf32
    int qb = qt * 128 + wm * 32;
    uint32_t afrag[2][2][4];
#pragma unroll
    for (int mt = 0; mt < 2; mt++)
#pragma unroll
        for (int kc = 0; kc < 2; kc++) {
            const uint32_t* base =
                (const uint32_t*)g_xcat + (size_t)(qb + mt * 16 + r) * 16 + kc * 8 + cg;
            afrag[mt][kc][0] = base[0];
            afrag[mt][kc][1] = base[8 * 16];
            afrag[mt][kc][2] = base[4];
            afrag[mt][kc][3] = base[8 * 16 + 4];
        }

    // Stage tile 0
    {
        const char* bsrc = (const char*)(g_dcat + (size_t)p0base * 4);
        uint32_t sbb = s2u(sd[0]);
#pragma unroll
        for (int i = tid; i < TILE * 4; i += THREADS)
            cpa16(sbb + i * 16, bsrc + i * 16);
        if (tid < 64)
            cpa16(s2u(sc[0]) + tid * 16, (const char*)(g_coeff + p0base) + tid * 16);
        CP_COMMIT();
    }

    float acc[2][2] = {{0.0f, 0.0f}, {0.0f, 0.0f}};
    int buf = 0;

    for (int it = 0; it < NT; ++it) {
        if (it + 1 < NT) {
            int p0 = p0base + (it + 1) * TILE;
            const char* bsrc = (const char*)(g_dcat + (size_t)p0 * 4);
            uint32_t sbb = s2u(sd[buf ^ 1]);
#pragma unroll
            for (int i = tid; i < TILE * 4; i += THREADS)
                cpa16(sbb + i * 16, bsrc + i * 16);
            if (tid < 64)
                cpa16(s2u(sc[buf ^ 1]) + tid * 16, (const char*)(g_coeff + p0) + tid * 16);
            CP_COMMIT();
            CP_WAIT1();   // tile `it` resident
        } else {
            CP_WAIT0();
        }
        __syncthreads();

        uint32_t sdb = s2u(sd[buf]);
        const float* scf = sc[buf];
#pragma unroll
        for (int nt = 0; nt < 16; nt++) {
            int n0 = wn * 128 + nt * 8;
            uint32_t b[4];
            lds128(sdb + (uint32_t)(n0 + r) * 64 + (uint32_t)cg * 16, b);
            float d0[4] = {0, 0, 0, 0}, d1[4] = {0, 0, 0, 0};
            mma_tf32(d0, afrag[0][0], b[0], b[1]);
            mma_tf32(d1, afrag[1][0], b[0], b[1]);
            mma_tf32(d0, afrag[0][1], b[2], b[3]);
            mma_tf32(d1, afrag[1][1], b[2], b[3]);

            float2 cj = *(const float2*)(scf + n0 + c2);
            acc[0][0] = fmaf(cj.x, ex2f(d0[0]), acc[0][0]);
            acc[0][0] = fmaf(cj.y, ex2f(d0[1]), acc[0][0]);
            acc[0][1] = fmaf(cj.x, ex2f(d0[2]), acc[0][1]);
            acc[0][1] = fmaf(cj.y, ex2f(d0[3]), acc[0][1]);
            acc[1][0] = fmaf(cj.x, ex2f(d1[0]), acc[1][0]);
            acc[1][0] = fmaf(cj.y, ex2f(d1[1]), acc[1][0]);
            acc[1][1] = fmaf(cj.x, ex2f(d1[2]), acc[1][1]);
            acc[1][1] = fmaf(cj.y, ex2f(d1[3]), acc[1][1]);
        }
        __syncthreads();  // done reading buf before restage
        buf ^= 1;
    }

    // Reduce over the 4 column-lanes (fixed order, deterministic)
#pragma unroll
    for (int mt = 0; mt < 2; mt++)
#pragma unroll
        for (int hh = 0; hh < 2; hh++) {
            float v = acc[mt][hh];
            v += __shfl_xor_sync(0xFFFFFFFFu, v, 1);
            v += __shfl_xor_sync(0xFFFFFFFFu, v, 2);
            acc[mt][hh] = v;
        }
    if (cg == 0) {
        int col = ds * 2 + wn;
        float* pc = g_partials + (size_t)col * NQ;
        pc[qb + r]          = acc[0][0];
        pc[qb + r + 8]      = acc[0][1];
        pc[qb + 16 + r]     = acc[1][0];
        pc[qb + 16 + r + 8] = acc[1][1];
    }

    // ---- last-CTA-per-qt finalization ----
    __threadfence();          // make this CTA's partials visible device-wide
    __syncthreads();
    __shared__ int s_last;
    if (tid == 0) {
        unsigned old = atomicInc(&g_cnt[qt], DS - 1);  // wraps to 0 on last
        s_last = (old == DS - 1);
    }
    __syncthreads();
    if (!s_last) return;

    // logsumw: reduce the 407 prep block sums (written before this kernel)
    __shared__ float redw[THREADS];
    {
        float s = g_wpart[tid];
        if (tid + 256 < PREP_BLOCKS) s += g_wpart[tid + 256];
        redw[tid] = s;
    }
    __syncthreads();
#pragma unroll
    for (int st = THREADS / 2; st > 0; st >>= 1) {
        if (tid < st) redw[tid] += redw[tid + st];
        __syncthreads();
    }
    float logsumw = logf(redw[0]);

    if (tid < 128) {
        int q = qt * 128 + tid;
        float S = 0.0f;
#pragma unroll
        for (int c = 0; c < NCOL; c++)
            S += __ldcg(&g_partials[(size_t)c * NQ + q]);   // fixed order

        float qn = 0.0f;
        const float4* row = (const float4*)(X + (size_t)q * DIM);
#pragma unroll
        for (int v = 0; v < 4; v++) {
            float4 p = row[v];
            qn += p.x * p.x + p.y * p.y + p.z * p.z + p.w * p.w;
        }
        const float LOG2PI = 1.8378770664093453f;
        out[q] = logf(S) - 0.5f * qn - 8.0f * LOG2PI - logsumw;
    }
}

// ---------------------------------------------------------------------------
extern "C" void kernel_launch(void* const* d_in, const int* in_sizes, int n_in,
                              void* d_out, int out_size) {
    const float* X    = (const float*)d_in[0];  // [2048, 16]
    const float* data = (const float*)d_in[1];  // [100000, 16]
    const float* w    = (const float*)d_in[2];  // [100000]
    float* out = (float*)d_out;                 // [2048]

    kde_prep_kernel<<<PREP_BLOCKS, PREP_THREADS>>>(data, w, X);
    kde_main_kernel<<<dim3(QTILES, DS), THREADS>>>(X, out);
}

// round 11
// speedup vs baseline: 1.1524x; 1.0183x over previous
#include <cuda_runtime.h>
#include <cuda_bf16.h>
#include <math.h>
#include <stdint.h>

#define NQ       2048
#define ND       100000
#define DIM      16
#define QTILES   16            // 2048 / 128 queries per CTA
#define DS       37            // data splits; 16*37 = 592 CTAs = 4/SM
#define TILE     256           // data points per smem tile
#define NT       11            // tiles per split
#define PTS_PER_SPLIT (TILE * NT)            // 2816
#define NPAD     (DS * PTS_PER_SPLIT)        // 104192
#define THREADS  256
#define PREP_BLOCKS  407       // NPAD / 256 exactly
#define PREP_THREADS 256
#define PROW     80            // padded partials row (74 used)

// ---- device scratch (no allocations allowed) ----
// g_dcat: per point, 16 tf32 words, PERMUTED: pos 4g+{0..3} = natural words
//         {g, g+4, g+8, g+12}. One LDS.128 per lane yields both k8 B
//         fragments (b0_kc0, b1_kc0, b0_kc1, b1_kc1) for m16n8k8 tf32.
__device__ float4 g_dcat[(size_t)NPAD * 4];
__device__ float g_xcat[(size_t)NQ * 16];   // y = x*log2e, tf32-rounded
__device__ float g_coeff[NPAD];             // w_j * exp(-0.5*||d||^2)
__device__ float g_partials[(size_t)NQ * PROW];
__device__ float g_wpart[PREP_BLOCKS];
__device__ float g_logsumw;

// ---- helpers ----
__device__ __forceinline__ uint32_t s2u(const void* p) {
    uint32_t a;
    asm("{ .reg .u64 t; cvta.to.shared.u64 t, %1; cvt.u32.u64 %0, t; }"
        : "=r"(a) : "l"(p));
    return a;
}
__device__ __forceinline__ void cpa16(uint32_t dst, const void* src) {
    asm volatile("cp.async.cg.shared.global [%0], [%1], 16;"
                 :: "r"(dst), "l"(src));
}
#define CP_COMMIT() asm volatile("cp.async.commit_group;" ::: "memory")
#define CP_WAIT0()  asm volatile("cp.async.wait_group 0;" ::: "memory")
#define CP_WAIT1()  asm volatile("cp.async.wait_group 1;" ::: "memory")

__device__ __forceinline__ float ex2f(float x) {
    float r; asm("ex2.approx.f32 %0, %1;" : "=f"(r) : "f"(x)); return r;
}
__device__ __forceinline__ float tf32r(float x) {
    float r; asm("cvt.rna.tf32.f32 %0, %1;" : "=f"(r) : "f"(x)); return r;
}
__device__ __forceinline__ void mma_tf32(float* d, const uint32_t* a,
                                         uint32_t b0, uint32_t b1) {
    asm volatile(
        "mma.sync.aligned.m16n8k8.row.col.f32.tf32.tf32.f32 "
        "{%0,%1,%2,%3}, {%4,%5,%6,%7}, {%8,%9}, {%0,%1,%2,%3};"
        : "+f"(d[0]), "+f"(d[1]), "+f"(d[2]), "+f"(d[3])
        : "r"(a[0]), "r"(a[1]), "r"(a[2]), "r"(a[3]), "r"(b0), "r"(b1));
}
__device__ __forceinline__ void lds128(uint32_t addr, uint32_t* v) {
    asm volatile("ld.shared.v4.u32 {%0,%1,%2,%3}, [%4];"
                 : "=r"(v[0]), "=r"(v[1]), "=r"(v[2]), "=r"(v[3]) : "r"(addr));
}

// ---------------------------------------------------------------------------
// Prep: point j -> tf32 permuted layout + coeff; query j (j<NQ) ->
// y = x*log2e tf32; block-partial sums of w.  (R7-proven, unchanged.)
// ---------------------------------------------------------------------------
__global__ __launch_bounds__(PREP_THREADS)
void kde_prep_kernel(const float* __restrict__ data,
                     const float* __restrict__ w,
                     const float* __restrict__ X) {
    int t = threadIdx.x;
    int j = blockIdx.x * PREP_THREADS + t;   // < NPAD (grid exact)

    float wd[16];
    float cj = 0.0f, wj = 0.0f;
    if (j < ND) {
        const float4* src = (const float4*)(data + (size_t)j * DIM);
        float dn = 0.0f;
#pragma unroll
        for (int v = 0; v < 4; v++) {
            float4 p = src[v];
            dn += p.x * p.x + p.y * p.y + p.z * p.z + p.w * p.w;
            wd[v * 4 + 0] = tf32r(p.x);
            wd[v * 4 + 1] = tf32r(p.y);
            wd[v * 4 + 2] = tf32r(p.z);
            wd[v * 4 + 3] = tf32r(p.w);
        }
        wj = w[j];
        cj = wj * __expf(-0.5f * dn);
    } else {
#pragma unroll
        for (int k = 0; k < 16; k++) wd[k] = 0.0f;
    }
    g_coeff[j] = cj;
    // permuted store: pos 4g+{0..3} = wd[g], wd[g+4], wd[g+8], wd[g+12]
#pragma unroll
    for (int g = 0; g < 4; g++) {
        float4 o;
        o.x = wd[g]; o.y = wd[g + 4]; o.z = wd[g + 8]; o.w = wd[g + 12];
        g_dcat[(size_t)j * 4 + g] = o;
    }

    if (j < NQ) {
        const float LOG2E = 1.4426950408889634f;
        const float4* src = (const float4*)(X + (size_t)j * DIM);
        float4* dst = (float4*)(g_xcat + (size_t)j * 16);
#pragma unroll
        for (int v = 0; v < 4; v++) {
            float4 p = src[v];
            float4 o;
            o.x = tf32r(p.x * LOG2E);
            o.y = tf32r(p.y * LOG2E);
            o.z = tf32r(p.z * LOG2E);
            o.w = tf32r(p.w * LOG2E);
            dst[v] = o;
        }
    }

    __shared__ float red[PREP_THREADS];
    red[t] = wj;
    __syncthreads();
#pragma unroll
    for (int s = PREP_THREADS / 2; s > 0; s >>= 1) {
        if (t < s) red[t] += red[t + s];
        __syncthreads();
    }
    if (t == 0) g_wpart[blockIdx.x] = red[0];
}

// ---------------------------------------------------------------------------
// Main: CTA (qt, ds): 128 queries x 2816 points, tf32 m16n8k8 (R7 loop,
// unchanged). CTA (0,0) additionally reduces g_wpart -> g_logsumw up front
// (hidden under the 46us wave; removes that work from the final kernel).
// ---------------------------------------------------------------------------
__global__ __launch_bounds__(THREADS, 4)
void kde_main_kernel() {
    __shared__ uint4 sd[2][TILE * 4];   // 2 x 16 KB, 64B per point (permuted)
    __shared__ float sc[2][TILE];

    int tid = threadIdx.x;
    int w = tid >> 5, lane = tid & 31;
    int wm = w >> 1, wn = w & 1;
    int qt = blockIdx.x, ds = blockIdx.y;
    int p0base = ds * PTS_PER_SPLIT;
    int r = lane >> 2, cg = lane & 3, c2 = cg * 2;

    // CTA (0,0), warp 0: logsumw (fixed order per lane -> deterministic)
    if (qt == 0 && ds == 0 && w == 0) {
        float s = 0.0f;
        for (int b = lane; b < PREP_BLOCKS; b += 32) s += g_wpart[b];
        s += __shfl_xor_sync(0xFFFFFFFFu, s, 16);
        s += __shfl_xor_sync(0xFFFFFFFFu, s, 8);
        s += __shfl_xor_sync(0xFFFFFFFFu, s, 4);
        s += __shfl_xor_sync(0xFFFFFFFFu, s, 2);
        s += __shfl_xor_sync(0xFFFFFFFFu, s, 1);
        if (lane == 0) g_logsumw = logf(s);
    }

    // A fragments: 32 queries (2 m-tiles) x 2 k-chunks, tf32
    int qb = qt * 128 + wm * 32;
    uint32_t afrag[2][2][4];
#pragma unroll
    for (int mt = 0; mt < 2; mt++)
#pragma unroll
        for (int kc = 0; kc < 2; kc++) {
            const uint32_t* base =
                (const uint32_t*)g_xcat + (size_t)(qb + mt * 16 + r) * 16 + kc * 8 + cg;
            afrag[mt][kc][0] = base[0];
            afrag[mt][kc][1] = base[8 * 16];
            afrag[mt][kc][2] = base[4];
            afrag[mt][kc][3] = base[8 * 16 + 4];
        }

    // Stage tile 0
    {
        const char* bsrc = (const char*)(g_dcat + (size_t)p0base * 4);
        uint32_t sbb = s2u(sd[0]);
#pragma unroll
        for (int i = tid; i < TILE * 4; i += THREADS)
            cpa16(sbb + i * 16, bsrc + i * 16);
        if (tid < 64)
            cpa16(s2u(sc[0]) + tid * 16, (const char*)(g_coeff + p0base) + tid * 16);
        CP_COMMIT();
    }

    float acc[2][2] = {{0.0f, 0.0f}, {0.0f, 0.0f}};
    int buf = 0;

    for (int it = 0; it < NT; ++it) {
        if (it + 1 < NT) {
            int p0 = p0base + (it + 1) * TILE;
            const char* bsrc = (const char*)(g_dcat + (size_t)p0 * 4);
            uint32_t sbb = s2u(sd[buf ^ 1]);
#pragma unroll
            for (int i = tid; i < TILE * 4; i += THREADS)
                cpa16(sbb + i * 16, bsrc + i * 16);
            if (tid < 64)
                cpa16(s2u(sc[buf ^ 1]) + tid * 16, (const char*)(g_coeff + p0) + tid * 16);
            CP_COMMIT();
            CP_WAIT1();   // tile `it` resident
        } else {
            CP_WAIT0();
        }
        __syncthreads();

        uint32_t sdb = s2u(sd[buf]);
        const float* scf = sc[buf];
#pragma unroll
        for (int nt = 0; nt < 16; nt++) {
            int n0 = wn * 128 + nt * 8;
            uint32_t b[4];
            lds128(sdb + (uint32_t)(n0 + r) * 64 + (uint32_t)cg * 16, b);
            float d0[4] = {0, 0, 0, 0}, d1[4] = {0, 0, 0, 0};
            // b[0],b[1] = k-chunk 0 fragment; b[2],b[3] = k-chunk 1
            mma_tf32(d0, afrag[0][0], b[0], b[1]);
            mma_tf32(d1, afrag[1][0], b[0], b[1]);
            mma_tf32(d0, afrag[0][1], b[2], b[3]);
            mma_tf32(d1, afrag[1][1], b[2], b[3]);

            float2 cj = *(const float2*)(scf + n0 + c2);
            acc[0][0] = fmaf(cj.x, ex2f(d0[0]), acc[0][0]);
            acc[0][0] = fmaf(cj.y, ex2f(d0[1]), acc[0][0]);
            acc[0][1] = fmaf(cj.x, ex2f(d0[2]), acc[0][1]);
            acc[0][1] = fmaf(cj.y, ex2f(d0[3]), acc[0][1]);
            acc[1][0] = fmaf(cj.x, ex2f(d1[0]), acc[1][0]);
            acc[1][0] = fmaf(cj.y, ex2f(d1[1]), acc[1][0]);
            acc[1][1] = fmaf(cj.x, ex2f(d1[2]), acc[1][1]);
            acc[1][1] = fmaf(cj.y, ex2f(d1[3]), acc[1][1]);
        }
        __syncthreads();  // done reading buf before restage
        buf ^= 1;
    }

    // Reduce over the 4 column-lanes (fixed order, deterministic)
#pragma unroll
    for (int mt = 0; mt < 2; mt++)
#pragma unroll
        for (int hh = 0; hh < 2; hh++) {
            float v = acc[mt][hh];
            v += __shfl_xor_sync(0xFFFFFFFFu, v, 1);
            v += __shfl_xor_sync(0xFFFFFFFFu, v, 2);
            acc[mt][hh] = v;
        }
    if (cg == 0) {
        int col = ds * 2 + wn;
        g_partials[(size_t)(qb + r) * PROW + col]          = acc[0][0];
        g_partials[(size_t)(qb + r + 8) * PROW + col]      = acc[0][1];
        g_partials[(size_t)(qb + 16 + r) * PROW + col]     = acc[1][0];
        g_partials[(size_t)(qb + 16 + r + 8) * PROW + col] = acc[1][1];
    }
}

// ---------------------------------------------------------------------------
// Finalize: warp per query; logsumw is a precomputed scalar.
//   log_density = log(S) - 0.5||x||^2 - 8*log(2*pi) - logsumw
// ---------------------------------------------------------------------------
__global__ __launch_bounds__(256)
void kde_final_kernel(const float* __restrict__ X,
                      float* __restrict__ out) {
    int t = threadIdx.x;
    int w = t >> 5, lane = t & 31;

    int q = blockIdx.x * 8 + w;
    const float* pr = g_partials + (size_t)q * PROW;
    float S = pr[lane] + pr[lane + 32];
    if (lane < DS * 2 - 64) S += pr[lane + 64];
    // fixed-order shfl reduction
    S += __shfl_xor_sync(0xFFFFFFFFu, S, 16);
    S += __shfl_xor_sync(0xFFFFFFFFu, S, 8);
    S += __shfl_xor_sync(0xFFFFFFFFu, S, 4);
    S += __shfl_xor_sync(0xFFFFFFFFu, S, 2);
    S += __shfl_xor_sync(0xFFFFFFFFu, S, 1);

    if (lane == 0) {
        float qn = 0.0f;
        const float4* row = (const float4*)(X + (size_t)q * DIM);
#pragma unroll
        for (int v = 0; v < 4; v++) {
            float4 p = row[v];
            qn += p.x * p.x + p.y * p.y + p.z * p.z + p.w * p.w;
        }
        const float LOG2PI = 1.8378770664093453f;
        out[q] = logf(S) - 0.5f * qn - 8.0f * LOG2PI - g_logsumw;
    }
}

// ---------------------------------------------------------------------------
extern "C" void kernel_launch(void* const* d_in, const int* in_sizes, int n_in,
                              void* d_out, int out_size) {
    const float* X    = (const float*)d_in[0];  // [2048, 16]
    const float* data = (const float*)d_in[1];  // [100000, 16]
    const float* w    = (const float*)d_in[2];  // [100000]
    float* out = (float*)d_out;                 // [2048]

    kde_prep_kernel<<<PREP_BLOCKS, PREP_THREADS>>>(data, w, X);
    kde_main_kernel<<<dim3(QTILES, DS), THREADS>>>();
    kde_final_kernel<<<NQ / 8, 256>>>(X, out);
}

// round 12
// speedup vs baseline: 1.1752x; 1.0198x over previous
#include <cuda_runtime.h>
#include <cuda_bf16.h>
#include <math.h>
#include <stdint.h>

#define NQ       2048
#define ND       100000
#define DIM      16
#define QTILES   16            // 2048 / 128 queries per CTA
#define DS       37            // data splits; 16*37 = 592 CTAs = 4/SM
#define TILE     256           // data points per smem tile
#define NT       11            // tiles per split
#define PTS_PER_SPLIT (TILE * NT)            // 2816
#define NPAD     (DS * PTS_PER_SPLIT)        // 104192
#define THREADS  256
#define PREP_BLOCKS  407       // NPAD / 256 exactly
#define PREP_THREADS 256
#define PROW     80            // padded partials row (74 used)

// ---- device scratch (no allocations allowed) ----
// g_dcat: per point, 16 tf32 words, PERMUTED: pos 4g+{0..3} = natural words
//         {g, g+4, g+8, g+12}. One LDS.128 per lane yields both k8 B
//         fragments (b0_kc0, b1_kc0, b0_kc1, b1_kc1) for m16n8k8 tf32.
__device__ float4 g_dcat[(size_t)NPAD * 4];
__device__ float g_coeff[NPAD];             // w_j * exp(-0.5*||d||^2)
__device__ float g_partials[(size_t)NQ * PROW];
__device__ float g_wpart[PREP_BLOCKS];
__device__ float g_logsumw;

// ---- helpers ----
__device__ __forceinline__ uint32_t s2u(const void* p) {
    uint32_t a;
    asm("{ .reg .u64 t; cvta.to.shared.u64 t, %1; cvt.u32.u64 %0, t; }"
        : "=r"(a) : "l"(p));
    return a;
}
__device__ __forceinline__ void cpa16(uint32_t dst, const void* src) {
    asm volatile("cp.async.cg.shared.global [%0], [%1], 16;"
                 :: "r"(dst), "l"(src));
}
#define CP_COMMIT() asm volatile("cp.async.commit_group;" ::: "memory")
#define CP_WAIT0()  asm volatile("cp.async.wait_group 0;" ::: "memory")
#define CP_WAIT1()  asm volatile("cp.async.wait_group 1;" ::: "memory")

__device__ __forceinline__ float ex2f(float x) {
    float r; asm("ex2.approx.f32 %0, %1;" : "=f"(r) : "f"(x)); return r;
}
__device__ __forceinline__ float tf32r(float x) {
    float r; asm("cvt.rna.tf32.f32 %0, %1;" : "=f"(r) : "f"(x)); return r;
}
__device__ __forceinline__ void mma_tf32(float* d, const uint32_t* a,
                                         uint32_t b0, uint32_t b1) {
    asm volatile(
        "mma.sync.aligned.m16n8k8.row.col.f32.tf32.tf32.f32 "
        "{%0,%1,%2,%3}, {%4,%5,%6,%7}, {%8,%9}, {%0,%1,%2,%3};"
        : "+f"(d[0]), "+f"(d[1]), "+f"(d[2]), "+f"(d[3])
        : "r"(a[0]), "r"(a[1]), "r"(a[2]), "r"(a[3]), "r"(b0), "r"(b1));
}
__device__ __forceinline__ void lds128(uint32_t addr, uint32_t* v) {
    asm volatile("ld.shared.v4.u32 {%0,%1,%2,%3}, [%4];"
                 : "=r"(v[0]), "=r"(v[1]), "=r"(v[2]), "=r"(v[3]) : "r"(addr));
}

// ---------------------------------------------------------------------------
// Prep: point j -> tf32 permuted layout + coeff; block-partial sums of w.
// (Query prep removed — main reads X directly.)
// ---------------------------------------------------------------------------
__global__ __launch_bounds__(PREP_THREADS)
void kde_prep_kernel(const float* __restrict__ data,
                     const float* __restrict__ w) {
    int t = threadIdx.x;
    int j = blockIdx.x * PREP_THREADS + t;   // < NPAD (grid exact)

    float wd[16];
    float cj = 0.0f, wj = 0.0f;
    if (j < ND) {
        const float4* src = (const float4*)(data + (size_t)j * DIM);
        float dn = 0.0f;
#pragma unroll
        for (int v = 0; v < 4; v++) {
            float4 p = src[v];
            dn += p.x * p.x + p.y * p.y + p.z * p.z + p.w * p.w;
            wd[v * 4 + 0] = tf32r(p.x);
            wd[v * 4 + 1] = tf32r(p.y);
            wd[v * 4 + 2] = tf32r(p.z);
            wd[v * 4 + 3] = tf32r(p.w);
        }
        wj = w[j];
        cj = wj * __expf(-0.5f * dn);
    } else {
#pragma unroll
        for (int k = 0; k < 16; k++) wd[k] = 0.0f;
    }
    g_coeff[j] = cj;
    // permuted store: pos 4g+{0..3} = wd[g], wd[g+4], wd[g+8], wd[g+12]
#pragma unroll
    for (int g = 0; g < 4; g++) {
        float4 o;
        o.x = wd[g]; o.y = wd[g + 4]; o.z = wd[g + 8]; o.w = wd[g + 12];
        g_dcat[(size_t)j * 4 + g] = o;
    }

    __shared__ float red[PREP_THREADS];
    red[t] = wj;
    __syncthreads();
#pragma unroll
    for (int s = PREP_THREADS / 2; s > 0; s >>= 1) {
        if (t < s) red[t] += red[t + s];
        __syncthreads();
    }
    if (t == 0) g_wpart[blockIdx.x] = red[0];
}

// ---------------------------------------------------------------------------
// Main: CTA (qt, ds): 128 queries x 2816 points, tf32 m16n8k8 (R7 loop).
// PDL: A fragments are computed from raw X (prep-independent) BEFORE
// cudaGridDependencySynchronize(); staging/g_wpart reads come after.
// ---------------------------------------------------------------------------
__global__ __launch_bounds__(THREADS, 4)
void kde_main_kernel(const float* __restrict__ X) {
    __shared__ uint4 sd[2][TILE * 4];   // 2 x 16 KB, 64B per point (permuted)
    __shared__ float sc[2][TILE];

    int tid = threadIdx.x;
    int w = tid >> 5, lane = tid & 31;
    int wm = w >> 1, wn = w & 1;
    int qt = blockIdx.x, ds = blockIdx.y;
    int p0base = ds * PTS_PER_SPLIT;
    int r = lane >> 2, cg = lane & 3, c2 = cg * 2;

    const float LOG2E = 1.4426950408889634f;

    // ---- prep-independent prolog: A fragments straight from X ----
    int qb = qt * 128 + wm * 32;
    uint32_t afrag[2][2][4];
#pragma unroll
    for (int mt = 0; mt < 2; mt++)
#pragma unroll
        for (int kc = 0; kc < 2; kc++) {
            int q0 = qb + mt * 16 + r;
            int k0 = kc * 8 + cg;
            afrag[mt][kc][0] = __float_as_uint(tf32r(X[(size_t)q0 * 16 + k0] * LOG2E));
            afrag[mt][kc][1] = __float_as_uint(tf32r(X[(size_t)(q0 + 8) * 16 + k0] * LOG2E));
            afrag[mt][kc][2] = __float_as_uint(tf32r(X[(size_t)q0 * 16 + k0 + 4] * LOG2E));
            afrag[mt][kc][3] = __float_as_uint(tf32r(X[(size_t)(q0 + 8) * 16 + k0 + 4] * LOG2E));
        }

    // ---- wait for prep kernel's writes to be visible ----
    cudaGridDependencySynchronize();

    // CTA (0,0), warp 0: logsumw (fixed order per lane -> deterministic)
    if (qt == 0 && ds == 0 && w == 0) {
        float s = 0.0f;
        for (int b = lane; b < PREP_BLOCKS; b += 32) s += g_wpart[b];
        s += __shfl_xor_sync(0xFFFFFFFFu, s, 16);
        s += __shfl_xor_sync(0xFFFFFFFFu, s, 8);
        s += __shfl_xor_sync(0xFFFFFFFFu, s, 4);
        s += __shfl_xor_sync(0xFFFFFFFFu, s, 2);
        s += __shfl_xor_sync(0xFFFFFFFFu, s, 1);
        if (lane == 0) g_logsumw = logf(s);
    }

    // Stage tile 0
    {
        const char* bsrc = (const char*)(g_dcat + (size_t)p0base * 4);
        uint32_t sbb = s2u(sd[0]);
#pragma unroll
        for (int i = tid; i < TILE * 4; i += THREADS)
            cpa16(sbb + i * 16, bsrc + i * 16);
        if (tid < 64)
            cpa16(s2u(sc[0]) + tid * 16, (const char*)(g_coeff + p0base) + tid * 16);
        CP_COMMIT();
    }

    float acc[2][2] = {{0.0f, 0.0f}, {0.0f, 0.0f}};
    int buf = 0;

    for (int it = 0; it < NT; ++it) {
        if (it + 1 < NT) {
            int p0 = p0base + (it + 1) * TILE;
            const char* bsrc = (const char*)(g_dcat + (size_t)p0 * 4);
            uint32_t sbb = s2u(sd[buf ^ 1]);
#pragma unroll
            for (int i = tid; i < TILE * 4; i += THREADS)
                cpa16(sbb + i * 16, bsrc + i * 16);
            if (tid < 64)
                cpa16(s2u(sc[buf ^ 1]) + tid * 16, (const char*)(g_coeff + p0) + tid * 16);
            CP_COMMIT();
            CP_WAIT1();   // tile `it` resident
        } else {
            CP_WAIT0();
        }
        __syncthreads();

        uint32_t sdb = s2u(sd[buf]);
        const float* scf = sc[buf];
#pragma unroll
        for (int nt = 0; nt < 16; nt++) {
            int n0 = wn * 128 + nt * 8;
            uint32_t b[4];
            lds128(sdb + (uint32_t)(n0 + r) * 64 + (uint32_t)cg * 16, b);
            float d0[4] = {0, 0, 0, 0}, d1[4] = {0, 0, 0, 0};
            // b[0],b[1] = k-chunk 0 fragment; b[2],b[3] = k-chunk 1
            mma_tf32(d0, afrag[0][0], b[0], b[1]);
            mma_tf32(d1, afrag[1][0], b[0], b[1]);
            mma_tf32(d0, afrag[0][1], b[2], b[3]);
            mma_tf32(d1, afrag[1][1], b[2], b[3]);

            float2 cj = *(const float2*)(scf + n0 + c2);
            acc[0][0] = fmaf(cj.x, ex2f(d0[0]), acc[0][0]);
            acc[0][0] = fmaf(cj.y, ex2f(d0[1]), acc[0][0]);
            acc[0][1] = fmaf(cj.x, ex2f(d0[2]), acc[0][1]);
            acc[0][1] = fmaf(cj.y, ex2f(d0[3]), acc[0][1]);
            acc[1][0] = fmaf(cj.x, ex2f(d1[0]), acc[1][0]);
            acc[1][0] = fmaf(cj.y, ex2f(d1[1]), acc[1][0]);
            acc[1][1] = fmaf(cj.x, ex2f(d1[2]), acc[1][1]);
            acc[1][1] = fmaf(cj.y, ex2f(d1[3]), acc[1][1]);
        }
        __syncthreads();  // done reading buf before restage
        buf ^= 1;
    }

    // Reduce over the 4 column-lanes (fixed order, deterministic)
#pragma unroll
    for (int mt = 0; mt < 2; mt++)
#pragma unroll
        for (int hh = 0; hh < 2; hh++) {
            float v = acc[mt][hh];
            v += __shfl_xor_sync(0xFFFFFFFFu, v, 1);
            v += __shfl_xor_sync(0xFFFFFFFFu, v, 2);
            acc[mt][hh] = v;
        }
    if (cg == 0) {
        int col = ds * 2 + wn;
        g_partials[(size_t)(qb + r) * PROW + col]          = acc[0][0];
        g_partials[(size_t)(qb + r + 8) * PROW + col]      = acc[0][1];
        g_partials[(size_t)(qb + 16 + r) * PROW + col]     = acc[1][0];
        g_partials[(size_t)(qb + 16 + r + 8) * PROW + col] = acc[1][1];
    }
}

// ---------------------------------------------------------------------------
// Finalize: warp per query. PDL: ||x||^2 (input-only) computed BEFORE
// cudaGridDependencySynchronize(); partials + logsumw read after.
//   log_density = log(S) - 0.5||x||^2 - 8*log(2*pi) - logsumw
// ---------------------------------------------------------------------------
__global__ __launch_bounds__(256)
void kde_final_kernel(const float* __restrict__ X,
                      float* __restrict__ out) {
    int t = threadIdx.x;
    int w = t >> 5, lane = t & 31;
    int q = blockIdx.x * 8 + w;

    // prep-independent prolog
    float qn = 0.0f;
    {
        const float4* row = (const float4*)(X + (size_t)q * DIM);
#pragma unroll
        for (int v = 0; v < 4; v++) {
            float4 p = row[v];
            qn += p.x * p.x + p.y * p.y + p.z * p.z + p.w * p.w;
        }
    }

    cudaGridDependencySynchronize();

    const float* pr = g_partials + (size_t)q * PROW;
    float S = pr[lane] + pr[lane + 32];
    if (lane < DS * 2 - 64) S += pr[lane + 64];
    // fixed-order shfl reduction
    S += __shfl_xor_sync(0xFFFFFFFFu, S, 16);
    S += __shfl_xor_sync(0xFFFFFFFFu, S, 8);
    S += __shfl_xor_sync(0xFFFFFFFFu, S, 4);
    S += __shfl_xor_sync(0xFFFFFFFFu, S, 2);
    S += __shfl_xor_sync(0xFFFFFFFFu, S, 1);

    if (lane == 0) {
        const float LOG2PI = 1.8378770664093453f;
        out[q] = logf(S) - 0.5f * qn - 8.0f * LOG2PI - g_logsumw;
    }
}

// ---------------------------------------------------------------------------
extern "C" void kernel_launch(void* const* d_in, const int* in_sizes, int n_in,
                              void* d_out, int out_size) {
    const float* X    = (const float*)d_in[0];  // [2048, 16]
    const float* data = (const float*)d_in[1];  // [100000, 16]
    const float* w    = (const float*)d_in[2];  // [100000]
    float* out = (float*)d_out;                 // [2048]

    kde_prep_kernel<<<PREP_BLOCKS, PREP_THREADS>>>(data, w);

    cudaLaunchAttribute attr[1];
    attr[0].id = cudaLaunchAttributeProgrammaticStreamSerialization;
    attr[0].val.programmaticStreamSerializationAllowed = 1;

    {
        cudaLaunchConfig_t cfg = {};
        cfg.gridDim = dim3(QTILES, DS);
        cfg.blockDim = dim3(THREADS);
        cfg.dynamicSmemBytes = 0;
        cfg.attrs = attr;
        cfg.numAttrs = 1;
        cudaLaunchKernelEx(&cfg, kde_main_kernel, X);
    }
    {
        cudaLaunchConfig_t cfg = {};
        cfg.gridDim = dim3(NQ / 8);
        cfg.blockDim = dim3(256);
        cfg.dynamicSmemBytes = 0;
        cfg.attrs = attr;
        cfg.numAttrs = 1;
        cudaLaunchKernelEx(&cfg, kde_final_kernel, X, out);
    }
}